// round 11
// baseline (speedup 1.0000x reference)
#include <cuda_runtime.h>
#include <cuda_fp16.h>
#include <math.h>
#include <stdint.h>

#define N_TOKENS 16384
#define HIDDEN   4096
#define NEXP     64
#define TOPK     8

#define BM       128          // tokens per CTA
#define BN       32           // experts per CTA (N-split: gridDim.y = 2)
#define TK       64           // k per stage
#define NT       (HIDDEN/TK)  // 64 stages
#define NTH      256          // 8 warps: 4 (M) x 2 (N), warp tile 32x16

// per-stage smem layout (bytes)
#define A_TERM   16384        // 128 rows x 64 k x 2B
#define A_STG    32768        // 2 fp16 terms
#define B_TERM   4096         // 32 rows x 64 k x 2B
#define B_STG    8192
#define STAGE_BYTES (A_STG + B_STG)   // 40960
#define SMEM_BYTES  (1024 + 2*STAGE_BYTES)  // 82944
#define CRS      36           // epilogue C row stride (floats)

#define SCALE_IN   2048.0f            // 2^11 on both x and W
#define SCALE_OUT  (1.0f/4194304.0f)  // exact 2^-22

// pre-split, pre-swizzled W: [stage][ehalf][term][32e x 64k]  (2 MB)
__device__ __align__(16) unsigned char g_wb[NT * 2 * B_STG];

// ---------------- helpers ----------------
__device__ __forceinline__ uint32_t smem_u32(const void* p) {
    uint32_t a;
    asm("{ .reg .u64 t; cvta.to.shared.u64 t, %1; cvt.u32.u64 %0, t; }" : "=r"(a) : "l"(p));
    return a;
}
__device__ __forceinline__ uint32_t sw128(uint32_t o) { return o ^ ((o >> 3) & 0x70); }

// pack two f32 into f16x2: lo = first arg, hi = second (first PTX src = high)
#define PACK_F16X2(res, lo, hi) \
    asm("cvt.rn.f16x2.f32 %0, %1, %2;" : "=r"(res) : "f"(hi), "f"(lo))

__device__ __forceinline__ void sts64(uint32_t a, uint32_t x, uint32_t y) {
    asm volatile("st.shared.v2.b32 [%0], {%1,%2};" :: "r"(a), "r"(x), "r"(y) : "memory");
}
__device__ __forceinline__ void cp_async16(uint32_t dst, const void* src) {
    asm volatile("cp.async.cg.shared.global [%0], [%1], 16;" :: "r"(dst), "l"(src) : "memory");
}
#define CP_COMMIT() asm volatile("cp.async.commit_group;" ::: "memory")
#define CP_WAIT0()  asm volatile("cp.async.wait_group 0;" ::: "memory")

__device__ __forceinline__ void ldsm_x4(uint32_t r[4], uint32_t addr) {
    asm volatile("ldmatrix.sync.aligned.m8n8.x4.shared.b16 {%0,%1,%2,%3}, [%4];"
        : "=r"(r[0]), "=r"(r[1]), "=r"(r[2]), "=r"(r[3]) : "r"(addr));
}
__device__ __forceinline__ void mma16816(float c[4], const uint32_t a[4],
                                         uint32_t b0, uint32_t b1) {
    asm volatile("mma.sync.aligned.m16n8k16.row.col.f32.f16.f16.f32 "
        "{%0,%1,%2,%3}, {%4,%5,%6,%7}, {%8,%9}, {%0,%1,%2,%3};"
        : "+f"(c[0]), "+f"(c[1]), "+f"(c[2]), "+f"(c[3])
        : "r"(a[0]), "r"(a[1]), "r"(a[2]), "r"(a[3]), "r"(b0), "r"(b1));
}

// x*2^11 = h0 + h1 (+ eps ~2^-22 rel). h0 roundtrip exact; r exact (Sterbenz).
__device__ __forceinline__ void splitf16(float v, float& f0, float& r) {
    f0 = __half2float(__float2half_rn(v));
    r  = v - f0;
}

// ---------------- W pre-split kernel ----------------
__global__ void wsplit_kernel(const float* __restrict__ W) {
    const int t = blockIdx.x;                 // stage (64 k)
    for (int item = threadIdx.x; item < NEXP * 16; item += blockDim.x) {
        const int e = item >> 4;              // global expert row 0..63
        const int k = (item & 15) * 4;        // k within stage
        const int eh = e >> 5, el = e & 31;
        float4 w = *(const float4*)(W + (size_t)e * HIDDEN + t * TK + k);
        float v[4] = {w.x * SCALE_IN, w.y * SCALE_IN, w.z * SCALE_IN, w.w * SCALE_IN};
        float f0[4], r[4];
#pragma unroll
        for (int i = 0; i < 4; i++) splitf16(v[i], f0[i], r[i]);
        uint32_t u0a, u0b, u1a, u1b;
        PACK_F16X2(u0a, f0[0], f0[1]); PACK_F16X2(u0b, f0[2], f0[3]);
        PACK_F16X2(u1a, r[0],  r[1]);  PACK_F16X2(u1b, r[2],  r[3]);
        unsigned char* dst = g_wb + (size_t)t * (2 * B_STG) + eh * B_STG;
        const uint32_t off = sw128((uint32_t)(el * 128 + k * 2));
        *(uint2*)(dst + 0 * B_TERM + off) = make_uint2(u0a, u0b);
        *(uint2*)(dst + 1 * B_TERM + off) = make_uint2(u1a, u1b);
    }
}

// MMA over one 64-k stage, warp tile 32x16.
// h0w0 -> accM (drained per stage); h0w1, h1w0 -> accC.
__device__ __forceinline__ void mma_stage(
    uint32_t Ab, uint32_t Bb, float accM[2][2][4], float accC[2][2][4],
    uint32_t arow0, uint32_t arow1, uint32_t brow,
    uint32_t colb, uint32_t swz)
{
#pragma unroll
    for (int k16 = 0; k16 < 4; k16++) {
        const uint32_t coff = (colb + 32u * k16) ^ swz;

        uint32_t B0[4], B1[4];
        ldsm_x4(B0, Bb + 0 * B_TERM + brow + coff);   // w0
        ldsm_x4(B1, Bb + 1 * B_TERM + brow + coff);   // w1

        uint32_t A00[4], A01[4];
        ldsm_x4(A00, Ab + 0 * A_TERM + arow0 + coff); // h0, m16 #0
        ldsm_x4(A01, Ab + 0 * A_TERM + arow1 + coff); // h0, m16 #1
        // main: h0*w0
        mma16816(accM[0][0], A00, B0[0], B0[2]);
        mma16816(accM[0][1], A00, B0[1], B0[3]);
        mma16816(accM[1][0], A01, B0[0], B0[2]);
        mma16816(accM[1][1], A01, B0[1], B0[3]);
        // corr: h0*w1
        mma16816(accC[0][0], A00, B1[0], B1[2]);
        mma16816(accC[0][1], A00, B1[1], B1[3]);
        mma16816(accC[1][0], A01, B1[0], B1[2]);
        mma16816(accC[1][1], A01, B1[1], B1[3]);

        uint32_t A10[4], A11[4];
        ldsm_x4(A10, Ab + 1 * A_TERM + arow0 + coff); // h1
        ldsm_x4(A11, Ab + 1 * A_TERM + arow1 + coff);
        // corr: h1*w0
        mma16816(accC[0][0], A10, B0[0], B0[2]);
        mma16816(accC[0][1], A10, B0[1], B0[3]);
        mma16816(accC[1][0], A11, B0[0], B0[2]);
        mma16816(accC[1][1], A11, B0[1], B0[3]);
    }
}

#define DRAIN_M()                                              \
    do {                                                       \
        _Pragma("unroll")                                      \
        for (int _i = 0; _i < 2; _i++)                         \
        _Pragma("unroll")                                      \
        for (int _j = 0; _j < 2; _j++)                         \
        _Pragma("unroll")                                      \
        for (int _q = 0; _q < 4; _q++) {                       \
            sum[_i][_j][_q] += accM[_i][_j][_q];               \
            accM[_i][_j][_q] = 0.0f;                           \
        }                                                      \
    } while (0)

// ---------------- GEMM kernel: 128 tokens x 32 experts per CTA ----------------
__global__ __launch_bounds__(NTH, 2) void router_kernel(
    const float* __restrict__ x,
    const float* __restrict__ b,
    float* __restrict__ out)   // writes router logits [N,64] only
{
    extern __shared__ __align__(16) char dsmem[];
    float* biasS = (float*)dsmem;                 // [32] this CTA's experts
    float* Cs    = (float*)(dsmem + 1024);        // epilogue [128][CRS]
    const uint32_t TBu = smem_u32(dsmem + 1024);

    const int tid = threadIdx.x;
    const int wid = tid >> 5;
    const int lid = tid & 31;
    const int block_m = blockIdx.x * BM;
    const int eh      = blockIdx.y;               // expert half 0/1

    // warp grid: 4 (M) x 2 (N), warp tile 32x16
    const int wm = (wid & 3) * 32;
    const int wn = (wid >> 2) * 16;

    // ldmatrix lane addressing
    const uint32_t lrow = (lid & 7) + ((lid >> 3) & 1) * 8;  // 0..15
    const uint32_t swz  = (lrow & 7) << 4;
    const uint32_t colb = (lid >> 4) * 16;
    const uint32_t arow0 = (wm + lrow) * 128;
    const uint32_t arow1 = arow0 + 16 * 128;
    const uint32_t brow  = (wn + lrow) * 128;

    // A conversion mapping: 32 contiguous k per thread, one row
    const int r  = tid >> 1;          // token row 0..127
    const int kq = (tid & 1) * 32;    // k base within stage
    const float* xrow = x + (size_t)(block_m + r) * HIDDEN + kq;

    float accM[2][2][4], accC[2][2][4], sum[2][2][4];
#pragma unroll
    for (int i = 0; i < 2; i++)
#pragma unroll
        for (int j = 0; j < 2; j++)
#pragma unroll
            for (int q = 0; q < 4; q++) {
                accM[i][j][q] = 0.0f; accC[i][j][q] = 0.0f; sum[i][j][q] = 0.0f;
            }

    const uint32_t stage[2] = {TBu, TBu + STAGE_BYTES};
    const unsigned char* wsrc = g_wb + eh * B_STG;

    // cp.async B(0) into stage 0  (8 KB: 2 x 16B per thread)
#pragma unroll
    for (int j = 0; j < 2; j++) {
        const int idx = tid + j * NTH;
        cp_async16(stage[0] + A_STG + idx * 16, wsrc + (size_t)idx * 16);
    }
    CP_COMMIT();

    // prefetch A(0)
    float4 ax[8];
#pragma unroll
    for (int j = 0; j < 8; j++) ax[j] = *(const float4*)(xrow + j * 4);

    if (tid < BN) biasS[tid] = b[eh * BN + tid];

    for (int t = 0; t < NT; ++t) {
        const int p = t & 1;
        const uint32_t Abase = stage[p];

        // convert + store A(t): 2 fp16 terms, x * 2^11
#pragma unroll
        for (int j = 0; j < 8; j++) {
            float v[4] = {ax[j].x * SCALE_IN, ax[j].y * SCALE_IN,
                          ax[j].z * SCALE_IN, ax[j].w * SCALE_IN};
            float f0[4], rr[4];
#pragma unroll
            for (int i = 0; i < 4; i++) splitf16(v[i], f0[i], rr[i]);
            uint32_t u0a, u0b, u1a, u1b;
            PACK_F16X2(u0a, f0[0], f0[1]); PACK_F16X2(u0b, f0[2], f0[3]);
            PACK_F16X2(u1a, rr[0], rr[1]); PACK_F16X2(u1b, rr[2], rr[3]);
            const uint32_t off = sw128((uint32_t)(r * 128 + (kq + j * 4) * 2));
            sts64(Abase + 0 * A_TERM + off, u0a, u0b);
            sts64(Abase + 1 * A_TERM + off, u1a, u1b);
        }

        // prefetch A(t+1)
        if (t + 1 < NT) {
            const float* xn = xrow + (size_t)(t + 1) * TK;
#pragma unroll
            for (int j = 0; j < 8; j++) ax[j] = *(const float4*)(xn + j * 4);
        }

        // MMA over previous stage, then drain main accumulator
        if (t > 0) {
            mma_stage(stage[p ^ 1], stage[p ^ 1] + A_STG,
                      accM, accC, arow0, arow1, brow, colb, swz);
            DRAIN_M();
        }

        CP_WAIT0();          // B(t) landed
        __syncthreads();     // stage p built; stage p^1 reads done

        // cp.async B(t+1) into stage p^1
        if (t + 1 < NT) {
            const unsigned char* src = wsrc + (size_t)(t + 1) * (2 * B_STG);
#pragma unroll
            for (int j = 0; j < 2; j++) {
                const int idx = tid + j * NTH;
                cp_async16(stage[p ^ 1] + A_STG + idx * 16, src + (size_t)idx * 16);
            }
            CP_COMMIT();
        }
    }
    // final stage (t = NT-1 odd -> stage[1])
    mma_stage(stage[1], stage[1] + A_STG,
              accM, accC, arow0, arow1, brow, colb, swz);
    DRAIN_M();

    // ---- dump C = sum + corrections (stage-0 area is dead)
#pragma unroll
    for (int im = 0; im < 2; im++)
#pragma unroll
        for (int in = 0; in < 2; in++) {
            const int r0 = wm + im * 16 + (lid >> 2);
            const int c0 = wn + in * 8 + (lid & 3) * 2;
            *(float2*)&Cs[r0 * CRS + c0] =
                make_float2(sum[im][in][0] + accC[im][in][0],
                            sum[im][in][1] + accC[im][in][1]);
            *(float2*)&Cs[(r0 + 8) * CRS + c0] =
                make_float2(sum[im][in][2] + accC[im][in][2],
                            sum[im][in][3] + accC[im][in][3]);
        }
    __syncthreads();

    // write router logits (+bias, rescaled) for this CTA's 32 experts
    {
        const int m  = tid >> 1;                  // 0..127
        const int c0 = (tid & 1) * 16;            // 0 or 16
        const int gm = block_m + m;
        float v[16];
#pragma unroll
        for (int e = 0; e < 16; e++)
            v[e] = Cs[m * CRS + c0 + e] * SCALE_OUT + biasS[c0 + e];
        float* dst = out + (size_t)gm * NEXP + eh * BN + c0;
#pragma unroll
        for (int e = 0; e < 16; e += 4)
            *(float4*)(dst + e) = make_float4(v[e], v[e + 1], v[e + 2], v[e + 3]);
    }
}

// ---------------- top-k / softmax / mask kernel ----------------
__global__ __launch_bounds__(256) void topk_kernel(float* __restrict__ out) {
    const int gm = blockIdx.x * 256 + threadIdx.x;   // token
    const float* row = out + (size_t)gm * NEXP;      // router logits (done)

    float v[NEXP];
#pragma unroll
    for (int e = 0; e < NEXP; e += 4) {
        float4 q = *(const float4*)(row + e);
        v[e] = q.x; v[e + 1] = q.y; v[e + 2] = q.z; v[e + 3] = q.w;
    }

    float* outWt   = out + (size_t)N_TOKENS * NEXP;
    float* outIdx  = outWt + (size_t)N_TOKENS * TOPK;
    float* outMask = outIdx + (size_t)N_TOKENS * TOPK;

    // top-8, strict > (first index on ties, matching jax top_k)
    unsigned long long used = 0ull;
    float vals[TOPK]; int idxs[TOPK];
#pragma unroll
    for (int k = 0; k < TOPK; k++) {
        float best = -INFINITY; int bi = 0;
#pragma unroll
        for (int e = 0; e < NEXP; e++) {
            const bool free_e = !((used >> e) & 1ull);
            if (free_e && v[e] > best) { best = v[e]; bi = e; }
        }
        used |= 1ull << bi;
        vals[k] = best; idxs[k] = bi;
    }
    const float mx = vals[0];
    float ex[TOPK], s = 0.0f;
#pragma unroll
    for (int k = 0; k < TOPK; k++) { ex[k] = expf(vals[k] - mx); s += ex[k]; }
    const float inv = 1.0f / s;

    *(float4*)(outWt + (size_t)gm * TOPK) =
        make_float4(ex[0] * inv, ex[1] * inv, ex[2] * inv, ex[3] * inv);
    *(float4*)(outWt + (size_t)gm * TOPK + 4) =
        make_float4(ex[4] * inv, ex[5] * inv, ex[6] * inv, ex[7] * inv);
    *(float4*)(outIdx + (size_t)gm * TOPK) =
        make_float4((float)idxs[0], (float)idxs[1], (float)idxs[2], (float)idxs[3]);
    *(float4*)(outIdx + (size_t)gm * TOPK + 4) =
        make_float4((float)idxs[4], (float)idxs[5], (float)idxs[6], (float)idxs[7]);
#pragma unroll
    for (int k = 0; k < TOPK; k++)
        outMask[(size_t)(idxs[k] * TOPK + k) * N_TOKENS + gm] = 1.0f;
}

extern "C" void kernel_launch(void* const* d_in, const int* in_sizes, int n_in,
                              void* d_out, int out_size)
{
    const float* x = (const float*)d_in[0];
    const float* W = (const float*)d_in[1];
    const float* b = (const float*)d_in[2];
    float* out = (float*)d_out;

    // zero the expert_mask region (rest of out fully overwritten)
    float* mask = out + (size_t)N_TOKENS * NEXP + 2 * (size_t)N_TOKENS * TOPK;
    cudaMemsetAsync(mask, 0, (size_t)NEXP * TOPK * N_TOKENS * sizeof(float), 0);

    wsplit_kernel<<<NT, 256>>>(W);

    cudaFuncSetAttribute(router_kernel,
                         cudaFuncAttributeMaxDynamicSharedMemorySize, SMEM_BYTES);
    dim3 grid(N_TOKENS / BM, 2);
    router_kernel<<<grid, NTH, SMEM_BYTES>>>(x, b, out);

    topk_kernel<<<N_TOKENS / 256, 256>>>(out);
}

// round 12
// speedup vs baseline: 2.0475x; 2.0475x over previous
#include <cuda_runtime.h>
#include <cuda_fp16.h>
#include <math.h>
#include <stdint.h>

#define N_TOKENS 16384
#define HIDDEN   4096
#define NEXP     64
#define TOPK     8

#define BM       128          // tokens per CTA
#define TK       64           // k per stage
#define NT       (HIDDEN/TK)  // 64 stages
#define NTH      512          // 16 warps: 4 (M) x 4 (N), warp tile 32x16
#define NSTG     3            // smem ring depth

// per-stage smem layout (bytes)
#define A_TERM   16384        // 128 rows x 64 k x 2B
#define A_STG    32768        // 2 fp16 terms
#define B_TERM   8192         // 64 rows x 64 k x 2B
#define B_STG    16384
#define STAGE_BYTES (A_STG + B_STG)        // 49152
#define SMEM_BYTES  (1024 + NSTG*STAGE_BYTES)  // 148480
#define CRS      72           // epilogue C row stride (floats)

#define SCALE_IN   2048.0f            // 2^11 on both x and W
#define SCALE_OUT  (1.0f/4194304.0f)  // exact 2^-22

// pre-split, pre-swizzled W (x2048, 2 fp16 terms): [stage][term][e][64k] (1 MB)
__device__ __align__(16) unsigned char g_wb[NT * B_STG];

// ---------------- helpers ----------------
__device__ __forceinline__ uint32_t smem_u32(const void* p) {
    uint32_t a;
    asm("{ .reg .u64 t; cvta.to.shared.u64 t, %1; cvt.u32.u64 %0, t; }" : "=r"(a) : "l"(p));
    return a;
}
__device__ __forceinline__ uint32_t sw128(uint32_t o) { return o ^ ((o >> 3) & 0x70); }

// pack two f32 into f16x2: lo = first arg, hi = second (first PTX src = high)
#define PACK_F16X2(res, lo, hi) \
    asm("cvt.rn.f16x2.f32 %0, %1, %2;" : "=r"(res) : "f"(hi), "f"(lo))

__device__ __forceinline__ void sts64(uint32_t a, uint32_t x, uint32_t y) {
    asm volatile("st.shared.v2.b32 [%0], {%1,%2};" :: "r"(a), "r"(x), "r"(y) : "memory");
}
__device__ __forceinline__ void cp_async16(uint32_t dst, const void* src) {
    asm volatile("cp.async.cg.shared.global [%0], [%1], 16;" :: "r"(dst), "l"(src) : "memory");
}
#define CP_COMMIT() asm volatile("cp.async.commit_group;" ::: "memory")
#define CP_WAIT0()  asm volatile("cp.async.wait_group 0;" ::: "memory")
#define CP_WAIT1()  asm volatile("cp.async.wait_group 1;" ::: "memory")

__device__ __forceinline__ void ldsm_x4(uint32_t r[4], uint32_t addr) {
    asm volatile("ldmatrix.sync.aligned.m8n8.x4.shared.b16 {%0,%1,%2,%3}, [%4];"
        : "=r"(r[0]), "=r"(r[1]), "=r"(r[2]), "=r"(r[3]) : "r"(addr));
}
__device__ __forceinline__ void mma16816(float c[4], const uint32_t a[4],
                                         uint32_t b0, uint32_t b1) {
    asm volatile("mma.sync.aligned.m16n8k16.row.col.f32.f16.f16.f32 "
        "{%0,%1,%2,%3}, {%4,%5,%6,%7}, {%8,%9}, {%0,%1,%2,%3};"
        : "+f"(c[0]), "+f"(c[1]), "+f"(c[2]), "+f"(c[3])
        : "r"(a[0]), "r"(a[1]), "r"(a[2]), "r"(a[3]), "r"(b0), "r"(b1));
}

// x*2^11 = h0 + h1 (+ eps ~2^-22 rel). h0 roundtrip exact; r exact (Sterbenz).
__device__ __forceinline__ void splitf16(float v, float& f0, float& r) {
    f0 = __half2float(__float2half_rn(v));
    r  = v - f0;
}

// ---------------- W pre-split kernel ----------------
__global__ void wsplit_kernel(const float* __restrict__ W) {
    const int t = blockIdx.x;                 // stage (64 k)
    unsigned char* dst = g_wb + (size_t)t * B_STG;
    for (int item = threadIdx.x; item < NEXP * 16; item += blockDim.x) {
        const int e = item >> 4;              // expert row
        const int k = (item & 15) * 4;        // k within stage
        float4 w = *(const float4*)(W + (size_t)e * HIDDEN + t * TK + k);
        float v[4] = {w.x * SCALE_IN, w.y * SCALE_IN, w.z * SCALE_IN, w.w * SCALE_IN};
        float f0[4], r[4];
#pragma unroll
        for (int i = 0; i < 4; i++) splitf16(v[i], f0[i], r[i]);
        uint32_t u0a, u0b, u1a, u1b;
        PACK_F16X2(u0a, f0[0], f0[1]); PACK_F16X2(u0b, f0[2], f0[3]);
        PACK_F16X2(u1a, r[0],  r[1]);  PACK_F16X2(u1b, r[2],  r[3]);
        const uint32_t off = sw128((uint32_t)(e * 128 + k * 2));
        *(uint2*)(dst + 0 * B_TERM + off) = make_uint2(u0a, u0b);
        *(uint2*)(dst + 1 * B_TERM + off) = make_uint2(u1a, u1b);
    }
}

// MMA over one 64-k stage, warp tile 32x16.
// h0w0 -> accM (drained per stage); h0w1, h1w0 -> accC.
__device__ __forceinline__ void mma_stage(
    uint32_t Ab, float accM[2][2][4], float accC[2][2][4],
    uint32_t arow0, uint32_t arow1, uint32_t brow,
    uint32_t colb, uint32_t swz)
{
    const uint32_t Bb = Ab + A_STG;
#pragma unroll
    for (int k16 = 0; k16 < 4; k16++) {
        const uint32_t coff = (colb + 32u * k16) ^ swz;

        uint32_t B0[4], B1[4];
        ldsm_x4(B0, Bb + 0 * B_TERM + brow + coff);   // w0
        ldsm_x4(B1, Bb + 1 * B_TERM + brow + coff);   // w1

        uint32_t A00[4], A01[4];
        ldsm_x4(A00, Ab + 0 * A_TERM + arow0 + coff); // h0, m16 #0
        ldsm_x4(A01, Ab + 0 * A_TERM + arow1 + coff); // h0, m16 #1
        // main: h0*w0
        mma16816(accM[0][0], A00, B0[0], B0[2]);
        mma16816(accM[0][1], A00, B0[1], B0[3]);
        mma16816(accM[1][0], A01, B0[0], B0[2]);
        mma16816(accM[1][1], A01, B0[1], B0[3]);
        // corr: h0*w1
        mma16816(accC[0][0], A00, B1[0], B1[2]);
        mma16816(accC[0][1], A00, B1[1], B1[3]);
        mma16816(accC[1][0], A01, B1[0], B1[2]);
        mma16816(accC[1][1], A01, B1[1], B1[3]);

        uint32_t A10[4], A11[4];
        ldsm_x4(A10, Ab + 1 * A_TERM + arow0 + coff); // h1
        ldsm_x4(A11, Ab + 1 * A_TERM + arow1 + coff);
        // corr: h1*w0
        mma16816(accC[0][0], A10, B0[0], B0[2]);
        mma16816(accC[0][1], A10, B0[1], B0[3]);
        mma16816(accC[1][0], A11, B0[0], B0[2]);
        mma16816(accC[1][1], A11, B0[1], B0[3]);
    }
}

#define DRAIN_M()                                              \
    do {                                                       \
        _Pragma("unroll")                                      \
        for (int _i = 0; _i < 2; _i++)                         \
        _Pragma("unroll")                                      \
        for (int _j = 0; _j < 2; _j++)                         \
        _Pragma("unroll")                                      \
        for (int _q = 0; _q < 4; _q++) {                       \
            sum[_i][_j][_q] += accM[_i][_j][_q];               \
            accM[_i][_j][_q] = 0.0f;                           \
        }                                                      \
    } while (0)

// ---------------- main kernel ----------------
__global__ __launch_bounds__(NTH, 1) void router_kernel(
    const float* __restrict__ x,
    const float* __restrict__ b,
    float* __restrict__ out)
{
    extern __shared__ __align__(16) char dsmem[];
    float* biasS = (float*)dsmem;                 // [64]
    const uint32_t TBu = smem_u32(dsmem + 1024);
    // epilogue C in stage-1 region (final MMA reads stage 0 only)
    float* Cs = (float*)(dsmem + 1024 + STAGE_BYTES);

    const int tid = threadIdx.x;
    const int wid = tid >> 5;
    const int lid = tid & 31;
    const int block_m = blockIdx.x * BM;

    // warp grid: 4 (M) x 4 (N), warp tile 32x16
    const int wm = (wid & 3) * 32;
    const int wn = (wid >> 2) * 16;

    // ldmatrix lane addressing
    const uint32_t lrow = (lid & 7) + ((lid >> 3) & 1) * 8;  // 0..15
    const uint32_t swz  = (lrow & 7) << 4;
    const uint32_t colb = (lid >> 4) * 16;
    const uint32_t arow0 = (wm + lrow) * 128;
    const uint32_t arow1 = arow0 + 16 * 128;
    const uint32_t brow  = (wn + lrow) * 128;

    // A conversion mapping: 16 contiguous k per thread, one row
    const int r  = tid >> 2;          // token row 0..127
    const int kq = (tid & 3) * 16;    // k base within stage
    const float* xrow = x + (size_t)(block_m + r) * HIDDEN + kq;
    const uint32_t aoff0 = sw128((uint32_t)(r * 128 + kq * 2));
    const uint32_t aoff1 = sw128((uint32_t)(r * 128 + kq * 2 + 8));
    const uint32_t aoff2 = sw128((uint32_t)(r * 128 + kq * 2 + 16));
    const uint32_t aoff3 = sw128((uint32_t)(r * 128 + kq * 2 + 24));

    float accM[2][2][4], accC[2][2][4], sum[2][2][4];
#pragma unroll
    for (int i = 0; i < 2; i++)
#pragma unroll
        for (int j = 0; j < 2; j++)
#pragma unroll
            for (int q = 0; q < 4; q++) {
                accM[i][j][q] = 0.0f; accC[i][j][q] = 0.0f; sum[i][j][q] = 0.0f;
            }

    const uint32_t stg[NSTG] = {TBu, TBu + STAGE_BYTES, TBu + 2 * STAGE_BYTES};
    const uint32_t aoffs[4] = {aoff0, aoff1, aoff2, aoff3};

    float4 ax[4];

    // convert+store one tile from ax into stage base
#define CONVERT_A(Abase)                                                       \
    do {                                                                       \
        _Pragma("unroll")                                                      \
        for (int j = 0; j < 4; j++) {                                          \
            float v[4] = {ax[j].x * SCALE_IN, ax[j].y * SCALE_IN,              \
                          ax[j].z * SCALE_IN, ax[j].w * SCALE_IN};             \
            float f0[4], rr[4];                                                \
            _Pragma("unroll")                                                  \
            for (int i = 0; i < 4; i++) splitf16(v[i], f0[i], rr[i]);          \
            uint32_t u0a, u0b, u1a, u1b;                                       \
            PACK_F16X2(u0a, f0[0], f0[1]); PACK_F16X2(u0b, f0[2], f0[3]);      \
            PACK_F16X2(u1a, rr[0], rr[1]); PACK_F16X2(u1b, rr[2], rr[3]);      \
            sts64((Abase) + 0 * A_TERM + aoffs[j], u0a, u0b);                  \
            sts64((Abase) + 1 * A_TERM + aoffs[j], u1a, u1b);                  \
        }                                                                      \
    } while (0)

    // ---- prologue: B0,B1 via cp.async; convert tiles 0 and 1; prefetch ax(2)
#pragma unroll
    for (int j = 0; j < 2; j++) {
        const int idx = tid + j * NTH;
        cp_async16(stg[0] + A_STG + idx * 16, g_wb + (size_t)idx * 16);
    }
    CP_COMMIT();
#pragma unroll
    for (int j = 0; j < 2; j++) {
        const int idx = tid + j * NTH;
        cp_async16(stg[1] + A_STG + idx * 16, g_wb + B_STG + (size_t)idx * 16);
    }
    CP_COMMIT();

#pragma unroll
    for (int j = 0; j < 4; j++) ax[j] = *(const float4*)(xrow + j * 4);
    CONVERT_A(stg[0]);
#pragma unroll
    for (int j = 0; j < 4; j++) ax[j] = *(const float4*)(xrow + TK + j * 4);
    CONVERT_A(stg[1]);
#pragma unroll
    for (int j = 0; j < 4; j++) ax[j] = *(const float4*)(xrow + 2 * TK + j * 4);

    if (tid < NEXP) biasS[tid] = b[tid];

    CP_WAIT1();              // B0 landed
    __syncthreads();

    // ---- main loop: iter t: MMA tile t-1; build tile t+1 (2-barrier slack)
    int srd = 0;             // stage of tile t-1
    int swr = 2;             // stage of tile t+1
    for (int t = 1; t < NT; ++t) {
        mma_stage(stg[srd], accM, accC, arow0, arow1, brow, colb, swz);
        DRAIN_M();

        if (t + 1 < NT) {
            CONVERT_A(stg[swr]);
            const unsigned char* src = g_wb + (size_t)(t + 1) * B_STG;
#pragma unroll
            for (int j = 0; j < 2; j++) {
                const int idx = tid + j * NTH;
                cp_async16(stg[swr] + A_STG + idx * 16, src + (size_t)idx * 16);
            }
            CP_COMMIT();
            if (t + 2 < NT) {
                const float* xn = xrow + (size_t)(t + 2) * TK;
#pragma unroll
                for (int j = 0; j < 4; j++) ax[j] = *(const float4*)(xn + j * 4);
            }
            CP_WAIT1();      // B(t) complete (G_t is second-newest)
        } else {
            CP_WAIT0();      // last B complete
        }
        __syncthreads();

        srd = (srd == NSTG - 1) ? 0 : srd + 1;
        swr = (swr == NSTG - 1) ? 0 : swr + 1;
    }
    // final tile NT-1 (stage srd == (NT-1)%3 == 0)
    mma_stage(stg[srd], accM, accC, arow0, arow1, brow, colb, swz);
    DRAIN_M();

    // ---- dump C = sum + corrections into stage-1 region (disjoint from stage 0)
#pragma unroll
    for (int im = 0; im < 2; im++)
#pragma unroll
        for (int in = 0; in < 2; in++) {
            const int r0 = wm + im * 16 + (lid >> 2);
            const int c0 = wn + in * 8 + (lid & 3) * 2;
            *(float2*)&Cs[r0 * CRS + c0] =
                make_float2(sum[im][in][0] + accC[im][in][0],
                            sum[im][in][1] + accC[im][in][1]);
            *(float2*)&Cs[(r0 + 8) * CRS + c0] =
                make_float2(sum[im][in][2] + accC[im][in][2],
                            sum[im][in][3] + accC[im][in][3]);
        }
    __syncthreads();

    if (tid < BM) {
        const int m  = tid;
        const int gm = block_m + m;
        float v[NEXP];
#pragma unroll
        for (int e = 0; e < NEXP; e++)
            v[e] = Cs[m * CRS + e] * SCALE_OUT + biasS[e];

        float* outR    = out;
        float* outWt   = out + (size_t)N_TOKENS * NEXP;
        float* outIdx  = outWt + (size_t)N_TOKENS * TOPK;
        float* outMask = outIdx + (size_t)N_TOKENS * TOPK;

        float* dst = outR + (size_t)gm * NEXP;
#pragma unroll
        for (int e = 0; e < NEXP; e += 4)
            *(float4*)(dst + e) = make_float4(v[e], v[e + 1], v[e + 2], v[e + 3]);

        // top-8, strict > (first index on ties, matching jax top_k)
        unsigned long long used = 0ull;
        float vals[TOPK]; int idxs[TOPK];
#pragma unroll
        for (int k = 0; k < TOPK; k++) {
            float best = -INFINITY; int bi = 0;
#pragma unroll
            for (int e = 0; e < NEXP; e++) {
                const bool free_e = !((used >> e) & 1ull);
                if (free_e && v[e] > best) { best = v[e]; bi = e; }
            }
            used |= 1ull << bi;
            vals[k] = best; idxs[k] = bi;
        }
        const float mx = vals[0];
        float ex[TOPK], s = 0.0f;
#pragma unroll
        for (int k = 0; k < TOPK; k++) { ex[k] = expf(vals[k] - mx); s += ex[k]; }
        const float inv = 1.0f / s;

        *(float4*)(outWt + (size_t)gm * TOPK) =
            make_float4(ex[0] * inv, ex[1] * inv, ex[2] * inv, ex[3] * inv);
        *(float4*)(outWt + (size_t)gm * TOPK + 4) =
            make_float4(ex[4] * inv, ex[5] * inv, ex[6] * inv, ex[7] * inv);
        *(float4*)(outIdx + (size_t)gm * TOPK) =
            make_float4((float)idxs[0], (float)idxs[1], (float)idxs[2], (float)idxs[3]);
        *(float4*)(outIdx + (size_t)gm * TOPK + 4) =
            make_float4((float)idxs[4], (float)idxs[5], (float)idxs[6], (float)idxs[7]);
#pragma unroll
        for (int k = 0; k < TOPK; k++)
            outMask[(size_t)(idxs[k] * TOPK + k) * N_TOKENS + gm] = 1.0f;
    }
}

extern "C" void kernel_launch(void* const* d_in, const int* in_sizes, int n_in,
                              void* d_out, int out_size)
{
    const float* x = (const float*)d_in[0];
    const float* W = (const float*)d_in[1];
    const float* b = (const float*)d_in[2];
    float* out = (float*)d_out;

    // zero the expert_mask region (rest of out fully overwritten)
    float* mask = out + (size_t)N_TOKENS * NEXP + 2 * (size_t)N_TOKENS * TOPK;
    cudaMemsetAsync(mask, 0, (size_t)NEXP * TOPK * N_TOKENS * sizeof(float), 0);

    wsplit_kernel<<<NT, 256>>>(W);

    cudaFuncSetAttribute(router_kernel,
                         cudaFuncAttributeMaxDynamicSharedMemorySize, SMEM_BYTES);
    router_kernel<<<N_TOKENS / BM, NTH, SMEM_BYTES>>>(x, b, out);
}

// round 13
// speedup vs baseline: 2.1829x; 1.0661x over previous
#include <cuda_runtime.h>
#include <cuda_fp16.h>
#include <math.h>
#include <stdint.h>

#define N_TOKENS 16384
#define HIDDEN   4096
#define NEXP     64
#define TOPK     8

#define BM       128          // tokens per CTA
#define TK       64           // k per stage
#define NT       (HIDDEN/TK)  // 64 stages
#define NTH      512          // 16 warps: 2 k-groups x (4M x 2N), warp tile 32x32
#define NSTG     3            // smem ring depth

// per-stage smem layout (bytes)
#define A_TERM   16384        // 128 rows x 64 k x 2B
#define A_STG    32768        // 2 fp16 terms
#define B_TERM   8192         // 64 rows x 64 k x 2B
#define B_STG    16384
#define STAGE_BYTES (A_STG + B_STG)        // 49152
#define SMEM_BYTES  (1024 + NSTG*STAGE_BYTES)  // 148480
#define CRS      72           // epilogue C row stride (floats)

#define SCALE_IN   2048.0f            // 2^11 on both x and W
#define SCALE_OUT  (1.0f/4194304.0f)  // exact 2^-22

// pre-split, pre-swizzled W (x2048, 2 fp16 terms): [stage][term][e][64k] (1 MB)
__device__ __align__(16) unsigned char g_wb[NT * B_STG];

// ---------------- helpers ----------------
__device__ __forceinline__ uint32_t smem_u32(const void* p) {
    uint32_t a;
    asm("{ .reg .u64 t; cvta.to.shared.u64 t, %1; cvt.u32.u64 %0, t; }" : "=r"(a) : "l"(p));
    return a;
}
__device__ __forceinline__ uint32_t sw128(uint32_t o) { return o ^ ((o >> 3) & 0x70); }

// pack two f32 into f16x2: lo = first arg, hi = second (first PTX src = high)
#define PACK_F16X2(res, lo, hi) \
    asm("cvt.rn.f16x2.f32 %0, %1, %2;" : "=r"(res) : "f"(hi), "f"(lo))

__device__ __forceinline__ void sts64(uint32_t a, uint32_t x, uint32_t y) {
    asm volatile("st.shared.v2.b32 [%0], {%1,%2};" :: "r"(a), "r"(x), "r"(y) : "memory");
}
__device__ __forceinline__ void cp_async16(uint32_t dst, const void* src) {
    asm volatile("cp.async.cg.shared.global [%0], [%1], 16;" :: "r"(dst), "l"(src) : "memory");
}
#define CP_COMMIT() asm volatile("cp.async.commit_group;" ::: "memory")
#define CP_WAIT0()  asm volatile("cp.async.wait_group 0;" ::: "memory")
#define CP_WAIT1()  asm volatile("cp.async.wait_group 1;" ::: "memory")

__device__ __forceinline__ void ldsm_x4(uint32_t r[4], uint32_t addr) {
    asm volatile("ldmatrix.sync.aligned.m8n8.x4.shared.b16 {%0,%1,%2,%3}, [%4];"
        : "=r"(r[0]), "=r"(r[1]), "=r"(r[2]), "=r"(r[3]) : "r"(addr));
}
__device__ __forceinline__ void mma16816(float c[4], const uint32_t a[4],
                                         uint32_t b0, uint32_t b1) {
    asm volatile("mma.sync.aligned.m16n8k16.row.col.f32.f16.f16.f32 "
        "{%0,%1,%2,%3}, {%4,%5,%6,%7}, {%8,%9}, {%0,%1,%2,%3};"
        : "+f"(c[0]), "+f"(c[1]), "+f"(c[2]), "+f"(c[3])
        : "r"(a[0]), "r"(a[1]), "r"(a[2]), "r"(a[3]), "r"(b0), "r"(b1));
}

// x*2^11 = h0 + h1 (+ eps ~2^-22 rel). h0 roundtrip exact; r exact (Sterbenz).
__device__ __forceinline__ void splitf16(float v, float& f0, float& r) {
    f0 = __half2float(__float2half_rn(v));
    r  = v - f0;
}

// ---------------- W pre-split kernel ----------------
__global__ void wsplit_kernel(const float* __restrict__ W) {
    const int t = blockIdx.x;                 // stage (64 k)
    unsigned char* dst = g_wb + (size_t)t * B_STG;
    for (int item = threadIdx.x; item < NEXP * 16; item += blockDim.x) {
        const int e = item >> 4;              // expert row
        const int k = (item & 15) * 4;        // k within stage
        float4 w = *(const float4*)(W + (size_t)e * HIDDEN + t * TK + k);
        float v[4] = {w.x * SCALE_IN, w.y * SCALE_IN, w.z * SCALE_IN, w.w * SCALE_IN};
        float f0[4], r[4];
#pragma unroll
        for (int i = 0; i < 4; i++) splitf16(v[i], f0[i], r[i]);
        uint32_t u0a, u0b, u1a, u1b;
        PACK_F16X2(u0a, f0[0], f0[1]); PACK_F16X2(u0b, f0[2], f0[3]);
        PACK_F16X2(u1a, r[0],  r[1]);  PACK_F16X2(u1b, r[2],  r[3]);
        const uint32_t off = sw128((uint32_t)(e * 128 + k * 2));
        *(uint2*)(dst + 0 * B_TERM + off) = make_uint2(u0a, u0b);
        *(uint2*)(dst + 1 * B_TERM + off) = make_uint2(u1a, u1b);
    }
}

// MMA over one 64-k stage, warp tile 32x32, merged accumulator.
// products h0w0, h0w1, h1w0 all -> acc (drained per stage).
__device__ __forceinline__ void mma_stage(
    uint32_t Ab, float acc[2][4][4],
    uint32_t arow0, uint32_t arow1, uint32_t brow0, uint32_t brow1,
    uint32_t colb, uint32_t swz)
{
    const uint32_t Bb = Ab + A_STG;
#pragma unroll
    for (int k16 = 0; k16 < 4; k16++) {
        const uint32_t coff = (colb + 32u * k16) ^ swz;

        uint32_t B00[4], B01[4], B10[4], B11[4];
        ldsm_x4(B00, Bb + 0 * B_TERM + brow0 + coff);   // w0, n16-0
        ldsm_x4(B01, Bb + 0 * B_TERM + brow1 + coff);   // w0, n16-1
        ldsm_x4(B10, Bb + 1 * B_TERM + brow0 + coff);   // w1, n16-0
        ldsm_x4(B11, Bb + 1 * B_TERM + brow1 + coff);   // w1, n16-1

        uint32_t A00[4], A01[4], A10[4], A11[4];
        ldsm_x4(A00, Ab + 0 * A_TERM + arow0 + coff);   // h0, m16-0
        ldsm_x4(A01, Ab + 0 * A_TERM + arow1 + coff);   // h0, m16-1
        ldsm_x4(A10, Ab + 1 * A_TERM + arow0 + coff);   // h1, m16-0
        ldsm_x4(A11, Ab + 1 * A_TERM + arow1 + coff);   // h1, m16-1

#pragma unroll
        for (int im = 0; im < 2; im++) {
            const uint32_t* Ah0 = (im == 0) ? A00 : A01;
            const uint32_t* Ah1 = (im == 0) ? A10 : A11;
            // h0*w0
            mma16816(acc[im][0], Ah0, B00[0], B00[2]);
            mma16816(acc[im][1], Ah0, B00[1], B00[3]);
            mma16816(acc[im][2], Ah0, B01[0], B01[2]);
            mma16816(acc[im][3], Ah0, B01[1], B01[3]);
            // h0*w1
            mma16816(acc[im][0], Ah0, B10[0], B10[2]);
            mma16816(acc[im][1], Ah0, B10[1], B10[3]);
            mma16816(acc[im][2], Ah0, B11[0], B11[2]);
            mma16816(acc[im][3], Ah0, B11[1], B11[3]);
            // h1*w0
            mma16816(acc[im][0], Ah1, B00[0], B00[2]);
            mma16816(acc[im][1], Ah1, B00[1], B00[3]);
            mma16816(acc[im][2], Ah1, B01[0], B01[2]);
            mma16816(acc[im][3], Ah1, B01[1], B01[3]);
        }
    }
}

#define DRAIN()                                                \
    do {                                                       \
        _Pragma("unroll")                                      \
        for (int _i = 0; _i < 2; _i++)                         \
        _Pragma("unroll")                                      \
        for (int _j = 0; _j < 4; _j++)                         \
        _Pragma("unroll")                                      \
        for (int _q = 0; _q < 4; _q++) {                       \
            sum[_i][_j][_q] += acc[_i][_j][_q];                \
            acc[_i][_j][_q] = 0.0f;                            \
        }                                                      \
    } while (0)

// ---------------- main kernel ----------------
__global__ __launch_bounds__(NTH, 1) void router_kernel(
    const float* __restrict__ x,
    const float* __restrict__ b,
    float* __restrict__ out)
{
    extern __shared__ __align__(16) char dsmem[];
    float* biasS = (float*)dsmem;                 // [64]
    const uint32_t TBu = smem_u32(dsmem + 1024);
    // epilogue C in stage-1 region (final MMA reads stage 0 only)
    float* Cs = (float*)(dsmem + 1024 + STAGE_BYTES);

    const int tid = threadIdx.x;
    const int wid = tid >> 5;
    const int lid = tid & 31;
    const int block_m = blockIdx.x * BM;

    // k-groups: group g MMAs tiles with tile%2==g. 8 warps per group,
    // warp grid 4 (M) x 2 (N), warp tile 32x32.
    const int group = wid >> 3;
    const int w8 = wid & 7;
    const int wm = (w8 & 3) * 32;
    const int wn = (w8 >> 2) * 32;

    // ldmatrix lane addressing
    const uint32_t lrow = (lid & 7) + ((lid >> 3) & 1) * 8;  // 0..15
    const uint32_t swz  = (lrow & 7) << 4;
    const uint32_t colb = (lid >> 4) * 16;
    const uint32_t arow0 = (wm + lrow) * 128;
    const uint32_t arow1 = arow0 + 16 * 128;
    const uint32_t brow0 = (wn + lrow) * 128;
    const uint32_t brow1 = brow0 + 16 * 128;

    // A conversion mapping: 16 contiguous k per thread, one row
    const int r  = tid >> 2;          // token row 0..127
    const int kq = (tid & 3) * 16;    // k base within stage
    const float* xrow = x + (size_t)(block_m + r) * HIDDEN + kq;
    const uint32_t aoffs[4] = {
        sw128((uint32_t)(r * 128 + kq * 2)),
        sw128((uint32_t)(r * 128 + kq * 2 + 8)),
        sw128((uint32_t)(r * 128 + kq * 2 + 16)),
        sw128((uint32_t)(r * 128 + kq * 2 + 24))};

    float acc[2][4][4], sum[2][4][4];
#pragma unroll
    for (int i = 0; i < 2; i++)
#pragma unroll
        for (int j = 0; j < 4; j++)
#pragma unroll
            for (int q = 0; q < 4; q++) { acc[i][j][q] = 0.0f; sum[i][j][q] = 0.0f; }

    const uint32_t stg[NSTG] = {TBu, TBu + STAGE_BYTES, TBu + 2 * STAGE_BYTES};

    float4 ax[4];

#define CONVERT_A(Abase)                                                       \
    do {                                                                       \
        _Pragma("unroll")                                                      \
        for (int j = 0; j < 4; j++) {                                          \
            float v[4] = {ax[j].x * SCALE_IN, ax[j].y * SCALE_IN,              \
                          ax[j].z * SCALE_IN, ax[j].w * SCALE_IN};             \
            float f0[4], rr[4];                                                \
            _Pragma("unroll")                                                  \
            for (int i = 0; i < 4; i++) splitf16(v[i], f0[i], rr[i]);          \
            uint32_t u0a, u0b, u1a, u1b;                                       \
            PACK_F16X2(u0a, f0[0], f0[1]); PACK_F16X2(u0b, f0[2], f0[3]);      \
            PACK_F16X2(u1a, rr[0], rr[1]); PACK_F16X2(u1b, rr[2], rr[3]);      \
            sts64((Abase) + 0 * A_TERM + aoffs[j], u0a, u0b);                  \
            sts64((Abase) + 1 * A_TERM + aoffs[j], u1a, u1b);                  \
        }                                                                      \
    } while (0)

    // ---- prologue: B0,B1 via cp.async; convert tiles 0,1; prefetch ax(2)
#pragma unroll
    for (int j = 0; j < 2; j++) {
        const int idx = tid + j * NTH;
        cp_async16(stg[0] + A_STG + idx * 16, g_wb + (size_t)idx * 16);
    }
    CP_COMMIT();
#pragma unroll
    for (int j = 0; j < 2; j++) {
        const int idx = tid + j * NTH;
        cp_async16(stg[1] + A_STG + idx * 16, g_wb + B_STG + (size_t)idx * 16);
    }
    CP_COMMIT();

#pragma unroll
    for (int j = 0; j < 4; j++) ax[j] = *(const float4*)(xrow + j * 4);
    CONVERT_A(stg[0]);
#pragma unroll
    for (int j = 0; j < 4; j++) ax[j] = *(const float4*)(xrow + TK + j * 4);
    CONVERT_A(stg[1]);
#pragma unroll
    for (int j = 0; j < 4; j++) ax[j] = *(const float4*)(xrow + 2 * TK + j * 4);

    if (tid < NEXP) biasS[tid] = b[tid];

    CP_WAIT1();              // B0 landed
    __syncthreads();

    // ---- main loop: period t: group ((t-1)&1) MMAs tile t-1; all build t+1
    int srd = 0;             // stage of tile t-1
    int swr = 2;             // stage of tile t+1
    for (int t = 1; t < NT; ++t) {
        if (((t - 1) & 1) == group) {
            mma_stage(stg[srd], acc, arow0, arow1, brow0, brow1, colb, swz);
            DRAIN();
        }

        if (t + 1 < NT) {
            CONVERT_A(stg[swr]);
            const unsigned char* src = g_wb + (size_t)(t + 1) * B_STG;
#pragma unroll
            for (int j = 0; j < 2; j++) {
                const int idx = tid + j * NTH;
                cp_async16(stg[swr] + A_STG + idx * 16, src + (size_t)idx * 16);
            }
            CP_COMMIT();
            if (t + 2 < NT) {
                const float* xn = xrow + (size_t)(t + 2) * TK;
#pragma unroll
                for (int j = 0; j < 4; j++) ax[j] = *(const float4*)(xn + j * 4);
            }
            CP_WAIT1();      // B(t) complete
        } else {
            CP_WAIT0();      // last B complete
        }
        __syncthreads();

        srd = (srd == NSTG - 1) ? 0 : srd + 1;
        swr = (swr == NSTG - 1) ? 0 : swr + 1;
    }
    // final: tile NT-1 (stage (NT-1)%3 == 0), owned by group ((NT-1)&1) == 1
    if (group == 1) {
        mma_stage(stg[0], acc, arow0, arow1, brow0, brow1, colb, swz);
        DRAIN();
    }

    // ---- combine groups into Cs (stage-1 region; disjoint from stage 0)
    if (group == 0) {
#pragma unroll
        for (int im = 0; im < 2; im++)
#pragma unroll
            for (int n8 = 0; n8 < 4; n8++) {
                const int r0 = wm + im * 16 + (lid >> 2);
                const int c0 = wn + n8 * 8 + (lid & 3) * 2;
                *(float2*)&Cs[r0 * CRS + c0] = make_float2(sum[im][n8][0], sum[im][n8][1]);
                *(float2*)&Cs[(r0 + 8) * CRS + c0] = make_float2(sum[im][n8][2], sum[im][n8][3]);
            }
    }
    __syncthreads();
    if (group == 1) {
#pragma unroll
        for (int im = 0; im < 2; im++)
#pragma unroll
            for (int n8 = 0; n8 < 4; n8++) {
                const int r0 = wm + im * 16 + (lid >> 2);
                const int c0 = wn + n8 * 8 + (lid & 3) * 2;
                float2 a0 = *(float2*)&Cs[r0 * CRS + c0];
                float2 a1 = *(float2*)&Cs[(r0 + 8) * CRS + c0];
                *(float2*)&Cs[r0 * CRS + c0] =
                    make_float2(a0.x + sum[im][n8][0], a0.y + sum[im][n8][1]);
                *(float2*)&Cs[(r0 + 8) * CRS + c0] =
                    make_float2(a1.x + sum[im][n8][2], a1.y + sum[im][n8][3]);
            }
    }
    __syncthreads();

    if (tid < BM) {
        const int m  = tid;
        const int gm = block_m + m;
        float v[NEXP];
#pragma unroll
        for (int e = 0; e < NEXP; e++)
            v[e] = Cs[m * CRS + e] * SCALE_OUT + biasS[e];

        float* outR    = out;
        float* outWt   = out + (size_t)N_TOKENS * NEXP;
        float* outIdx  = outWt + (size_t)N_TOKENS * TOPK;
        float* outMask = outIdx + (size_t)N_TOKENS * TOPK;

        float* dst = outR + (size_t)gm * NEXP;
#pragma unroll
        for (int e = 0; e < NEXP; e += 4)
            *(float4*)(dst + e) = make_float4(v[e], v[e + 1], v[e + 2], v[e + 3]);

        // top-8, strict > (first index on ties, matching jax top_k)
        unsigned long long used = 0ull;
        float vals[TOPK]; int idxs[TOPK];
#pragma unroll
        for (int k = 0; k < TOPK; k++) {
            float best = -INFINITY; int bi = 0;
#pragma unroll
            for (int e = 0; e < NEXP; e++) {
                const bool free_e = !((used >> e) & 1ull);
                if (free_e && v[e] > best) { best = v[e]; bi = e; }
            }
            used |= 1ull << bi;
            vals[k] = best; idxs[k] = bi;
        }
        const float mx = vals[0];
        float ex[TOPK], s = 0.0f;
#pragma unroll
        for (int k = 0; k < TOPK; k++) { ex[k] = expf(vals[k] - mx); s += ex[k]; }
        const float inv = 1.0f / s;

        *(float4*)(outWt + (size_t)gm * TOPK) =
            make_float4(ex[0] * inv, ex[1] * inv, ex[2] * inv, ex[3] * inv);
        *(float4*)(outWt + (size_t)gm * TOPK + 4) =
            make_float4(ex[4] * inv, ex[5] * inv, ex[6] * inv, ex[7] * inv);
        *(float4*)(outIdx + (size_t)gm * TOPK) =
            make_float4((float)idxs[0], (float)idxs[1], (float)idxs[2], (float)idxs[3]);
        *(float4*)(outIdx + (size_t)gm * TOPK + 4) =
            make_float4((float)idxs[4], (float)idxs[5], (float)idxs[6], (float)idxs[7]);
#pragma unroll
        for (int k = 0; k < TOPK; k++)
            outMask[(size_t)(idxs[k] * TOPK + k) * N_TOKENS + gm] = 1.0f;
    }
}

extern "C" void kernel_launch(void* const* d_in, const int* in_sizes, int n_in,
                              void* d_out, int out_size)
{
    const float* x = (const float*)d_in[0];
    const float* W = (const float*)d_in[1];
    const float* b = (const float*)d_in[2];
    float* out = (float*)d_out;

    // zero the expert_mask region (rest of out fully overwritten)
    float* mask = out + (size_t)N_TOKENS * NEXP + 2 * (size_t)N_TOKENS * TOPK;
    cudaMemsetAsync(mask, 0, (size_t)NEXP * TOPK * N_TOKENS * sizeof(float), 0);

    wsplit_kernel<<<NT, 256>>>(W);

    cudaFuncSetAttribute(router_kernel,
                         cudaFuncAttributeMaxDynamicSharedMemorySize, SMEM_BYTES);
    router_kernel<<<N_TOKENS / BM, NTH, SMEM_BYTES>>>(x, b, out);
}